// round 4
// baseline (speedup 1.0000x reference)
#include <cuda_runtime.h>
#include <math.h>

#define TT 128
#define BB 32
#define EE 512
#define HH 512
#define UU 1024
#define VV 10000
#define G4 2048   // 4*H

#define NBLK 128          // persistent blocks (16 ntiles x 8 ksplits)
#define NTILES 16
#define KSPLIT 8
#define NRED 64           // reducer blocks
#define PAD_HS 44         // hs row stride (floats); 176B, 16B-aligned, low conflicts

// ---------------- scratch (static device globals; no allocation) ----------------
__device__ __align__(128) float g_X1 [TT*BB*G4];
__device__ __align__(128) float g_H1 [TT*BB*HH];
__device__ __align__(128) float g_S  [TT*BB*UU];
__device__ __align__(128) float g_CTX[TT*BB*HH];
__device__ __align__(128) float g_X2 [TT*BB*G4];
__device__ __align__(128) float g_HS [TT*BB*HH];
__device__ __align__(128) float g_P  [2*KSPLIT*BB*G4];   // parity-buffered partials [p][s][b][col]

__device__ unsigned g_prod_flag[2][NBLK];
__device__ unsigned g_red_flag [2][NRED];

// ---------------- flag reset (before each recurrence launch) ----------------
__global__ void flags_reset()
{
    int i = threadIdx.x;
    if (i < NBLK) { g_prod_flag[0][i] = 0; g_prod_flag[1][i] = 0; }
    if (i < NRED) { g_red_flag[0][i] = 0;  g_red_flag[1][i] = 0; }
}

// ---------------- f32x2 helpers ----------------
__device__ __forceinline__ unsigned long long pack2(float x) {
    unsigned long long r;
    asm("mov.b64 %0, {%1, %1};" : "=l"(r) : "r"(__float_as_uint(x)));
    return r;
}
__device__ __forceinline__ void fma2(unsigned long long& d,
                                     unsigned long long a, unsigned long long b) {
    asm("fma.rn.f32x2 %0, %1, %2, %0;" : "+l"(d) : "l"(a), "l"(b));
}
__device__ __forceinline__ void unpack2(unsigned long long v, float& lo, float& hi) {
    unsigned a, b;
    asm("mov.b64 {%0, %1}, %2;" : "=r"(a), "=r"(b) : "l"(v));
    lo = __uint_as_float(a); hi = __uint_as_float(b);
}

__device__ __forceinline__ float sigmoidf_(float x) { return 1.f / (1.f + expf(-x)); }

// ---------------- persistent LSTM recurrence -----------------------------------
// Producers (all 128 blocks): partial GEMV h_{t-1} @ Whh^T for (ntile, ks) slice.
// Reducers (blocks 0..63): 8-way k reduction + pointwise LSTM, c held in registers.
// Sync: per-block epoch flags (no atomics), parity double-buffered partials.
__global__ __launch_bounds__(128)
void lstm_seq(const float* __restrict__ Xpre,   // [T][B][G4]
              const float* __restrict__ Whh,    // [G4][H]
              const float* __restrict__ h0row,  // [B][H]
              const float* __restrict__ c0row,  // [B][H]
              float* __restrict__ Hout)         // [T][B][H]
{
    __shared__ float4 Wt[32 * 65];        // Wt[nq][kk] = W[n0+4nq+0..3][k0+kk]
    __shared__ float  hs[64 * PAD_HS];    // hs[kk][b]

    const int bid   = blockIdx.x;
    const int tid   = threadIdx.x;
    const int ntile = bid & (NTILES - 1);
    const int ks    = bid >> 4;
    const int n0    = ntile * 128;
    const int k0    = ks * 64;

    // stage W tile once (invariant across timesteps)
    for (int idx = tid; idx < 2048; idx += 128) {
        int nq = idx >> 6, kk = idx & 63;
        int n  = n0 + nq * 4;
        Wt[nq * 65 + kk] = make_float4(
            Whh[(size_t)(n + 0) * HH + k0 + kk],
            Whh[(size_t)(n + 1) * HH + k0 + kk],
            Whh[(size_t)(n + 2) * HH + k0 + kk],
            Whh[(size_t)(n + 3) * HH + k0 + kk]);
    }

    const int nq = tid >> 2;   // 0..31 : n-group (4 n)
    const int bq = tid & 3;    // 0..3  : b-group (8 b)
    const int hb = tid >> 2;   // staging: b row
    const int hk = tid & 3;    // staging: k sub-group

    // reducer state: 2 cells per thread, c in registers
    const bool is_red = (bid < NRED);
    int rb0 = 0, rh0 = 0, rb1 = 0, rh1 = 0;
    float cv0 = 0.f, cv1 = 0.f;
    if (is_red) {
        int cell0 = bid * 256 + tid;
        int cell1 = cell0 + 128;
        rb0 = cell0 >> 9; rh0 = cell0 & 511;
        rb1 = cell1 >> 9; rh1 = cell1 & 511;
        cv0 = c0row[rb0 * HH + rh0];
        cv1 = c0row[rb1 * HH + rh1];
    }

    __syncthreads();

    for (int t = 0; t < TT; t++) {
        const int p = t & 1;
        const float* hprev;
        if (t == 0) {
            hprev = h0row;
        } else {
            hprev = Hout + (size_t)(t - 1) * BB * HH;
            // wait for all reducers of step t-1 (parity p^1). Also covers WAR on P[p].
            if (tid < NRED) {
                volatile unsigned* f = &g_red_flag[p ^ 1][tid];
                const unsigned tgt = (unsigned)t;
                while (*f < tgt) { }
            }
            __syncthreads();
        }

        // stage h slice -> hs[kk][b] (transposed)
        #pragma unroll
        for (int r = 0; r < 4; r++) {
            int kg = hk * 4 + r;                 // 0..15
            float4 v = *(const float4*)(hprev + (size_t)hb * HH + k0 + kg * 4);
            int kk = kg * 4;
            hs[(kk + 0) * PAD_HS + hb] = v.x;
            hs[(kk + 1) * PAD_HS + hb] = v.y;
            hs[(kk + 2) * PAD_HS + hb] = v.z;
            hs[(kk + 3) * PAD_HS + hb] = v.w;
        }
        __syncthreads();

        // ---- 4n x 8b x 64k with packed f32x2 FMA ----
        unsigned long long acc[4][4];
        #pragma unroll
        for (int i = 0; i < 4; i++)
            #pragma unroll
            for (int j = 0; j < 4; j++) acc[i][j] = 0ull;

        #pragma unroll 4
        for (int kk = 0; kk < 64; kk++) {
            float4 wv = Wt[nq * 65 + kk];
            const ulonglong2* hp = (const ulonglong2*)&hs[kk * PAD_HS + bq * 8];
            ulonglong2 hA = hp[0];   // b pairs (0,1)
            ulonglong2 hB = hp[1];   // b pairs (2,3)
            unsigned long long w0 = pack2(wv.x);
            unsigned long long w1 = pack2(wv.y);
            unsigned long long w2 = pack2(wv.z);
            unsigned long long w3 = pack2(wv.w);
            fma2(acc[0][0], w0, hA.x); fma2(acc[0][1], w0, hA.y);
            fma2(acc[0][2], w0, hB.x); fma2(acc[0][3], w0, hB.y);
            fma2(acc[1][0], w1, hA.x); fma2(acc[1][1], w1, hA.y);
            fma2(acc[1][2], w1, hB.x); fma2(acc[1][3], w1, hB.y);
            fma2(acc[2][0], w2, hA.x); fma2(acc[2][1], w2, hA.y);
            fma2(acc[2][2], w2, hB.x); fma2(acc[2][3], w2, hB.y);
            fma2(acc[3][0], w3, hA.x); fma2(acc[3][1], w3, hA.y);
            fma2(acc[3][2], w3, hB.x); fma2(acc[3][3], w3, hB.y);
        }

        // ---- store partials: P[p][ks][b][col] ----
        float* Pb = g_P + (((size_t)p * KSPLIT + ks) * BB) * G4;
        #pragma unroll
        for (int j = 0; j < 4; j++) {
            float l0, h0v, l1, h1v, l2, h2v, l3, h3v;
            unpack2(acc[0][j], l0, h0v);
            unpack2(acc[1][j], l1, h1v);
            unpack2(acc[2][j], l2, h2v);
            unpack2(acc[3][j], l3, h3v);
            int b = bq * 8 + 2 * j;
            *(float4*)(Pb + (size_t)b       * G4 + n0 + nq * 4) = make_float4(l0, l1, l2, l3);
            *(float4*)(Pb + (size_t)(b + 1) * G4 + n0 + nq * 4) = make_float4(h0v, h1v, h2v, h3v);
        }
        __threadfence();
        __syncthreads();
        if (tid == 0) *(volatile unsigned*)&g_prod_flag[p][bid] = (unsigned)(t + 1);

        // ---- reduce + pointwise (blocks 0..63) ----
        if (is_red) {
            const float* xp = Xpre + (size_t)t * BB * G4;
            // prefetch gate pre-activations (independent of partials)
            float a0 = xp[(size_t)rb0 * G4 + rh0];
            float a1 = xp[(size_t)rb0 * G4 + 512  + rh0];
            float a2 = xp[(size_t)rb0 * G4 + 1024 + rh0];
            float a3 = xp[(size_t)rb0 * G4 + 1536 + rh0];
            float d0 = xp[(size_t)rb1 * G4 + rh1];
            float d1 = xp[(size_t)rb1 * G4 + 512  + rh1];
            float d2 = xp[(size_t)rb1 * G4 + 1024 + rh1];
            float d3 = xp[(size_t)rb1 * G4 + 1536 + rh1];

            // wait for all producers of this step
            {
                volatile unsigned* f = &g_prod_flag[p][tid];
                const unsigned tgt = (unsigned)(t + 1);
                while (*f < tgt) { }
            }
            __syncthreads();

            #pragma unroll
            for (int s = 0; s < KSPLIT; s++) {
                const float* P0 = g_P + (((size_t)p * KSPLIT + s) * BB + rb0) * G4;
                a0 += __ldcg(P0 + rh0);
                a1 += __ldcg(P0 + 512  + rh0);
                a2 += __ldcg(P0 + 1024 + rh0);
                a3 += __ldcg(P0 + 1536 + rh0);
                const float* P1 = g_P + (((size_t)p * KSPLIT + s) * BB + rb1) * G4;
                d0 += __ldcg(P1 + rh1);
                d1 += __ldcg(P1 + 512  + rh1);
                d2 += __ldcg(P1 + 1024 + rh1);
                d3 += __ldcg(P1 + 1536 + rh1);
            }

            a0 = sigmoidf_(a0); a1 = sigmoidf_(a1); a2 = tanhf(a2); a3 = sigmoidf_(a3);
            cv0 = a1 * cv0 + a0 * a2;
            float ho0 = a3 * tanhf(cv0);

            d0 = sigmoidf_(d0); d1 = sigmoidf_(d1); d2 = tanhf(d2); d3 = sigmoidf_(d3);
            cv1 = d1 * cv1 + d0 * d2;
            float ho1 = d3 * tanhf(cv1);

            float* ho = Hout + (size_t)t * BB * HH;
            ho[(size_t)rb0 * HH + rh0] = ho0;
            ho[(size_t)rb1 * HH + rh1] = ho1;

            __threadfence();
            __syncthreads();
            if (tid == 0) *(volatile unsigned*)&g_red_flag[p][bid] = (unsigned)(t + 1);
        }
    }
}

// ---------------- SGEMM  C = A(MxK) * B(NxK)^T + bias1 + bias2 ----------------
__global__ __launch_bounds__(256)
void sgemm_tn(const float* __restrict__ A, const float* __restrict__ B,
              float* __restrict__ C,
              const float* __restrict__ bias1, const float* __restrict__ bias2,
              int M, int N, int K, int lda, int ldb, int ldc,
              long long aBS, long long bBS, long long cBS)
{
    __shared__ float As[16][64];
    __shared__ float Bs[16][64];

    const int tid = threadIdx.x;
    const int tx = tid & 15;
    const int ty = tid >> 4;
    const int m0 = blockIdx.y * 64;
    const int n0 = blockIdx.x * 64;

    const float* Ab = A + (long long)blockIdx.z * aBS;
    const float* Bb = B + (long long)blockIdx.z * bBS;
    float*       Cb = C + (long long)blockIdx.z * cBS;

    const int lr = tid >> 2;
    const int lk = (tid & 3) << 2;

    float acc[4][4];
    #pragma unroll
    for (int i = 0; i < 4; i++)
        #pragma unroll
        for (int j = 0; j < 4; j++) acc[i][j] = 0.f;

    for (int kt = 0; kt < K; kt += 16) {
        {
            int m = m0 + lr;
            float4 v = make_float4(0.f, 0.f, 0.f, 0.f);
            if (m < M) v = *(const float4*)(Ab + (size_t)m * lda + kt + lk);
            As[lk + 0][lr] = v.x; As[lk + 1][lr] = v.y;
            As[lk + 2][lr] = v.z; As[lk + 3][lr] = v.w;
        }
        {
            int n = n0 + lr;
            float4 v = make_float4(0.f, 0.f, 0.f, 0.f);
            if (n < N) v = *(const float4*)(Bb + (size_t)n * ldb + kt + lk);
            Bs[lk + 0][lr] = v.x; Bs[lk + 1][lr] = v.y;
            Bs[lk + 2][lr] = v.z; Bs[lk + 3][lr] = v.w;
        }
        __syncthreads();
        #pragma unroll
        for (int k = 0; k < 16; k++) {
            float a[4], b[4];
            *(float4*)a = *(const float4*)&As[k][ty << 2];
            *(float4*)b = *(const float4*)&Bs[k][tx << 2];
            #pragma unroll
            for (int i = 0; i < 4; i++)
                #pragma unroll
                for (int j = 0; j < 4; j++)
                    acc[i][j] += a[i] * b[j];
        }
        __syncthreads();
    }

    #pragma unroll
    for (int i = 0; i < 4; i++) {
        int m = m0 + (ty << 2) + i;
        if (m >= M) continue;
        #pragma unroll
        for (int j = 0; j < 4; j++) {
            int n = n0 + (tx << 2) + j;
            if (n < N) {
                float v = acc[i][j];
                if (bias1) v += bias1[n];
                if (bias2) v += bias2[n];
                Cb[(size_t)m * ldc + n] = v;
            }
        }
    }
}

// ---------------- SGEMM  C = A(MxK) * B(KxN) ----------------
__global__ __launch_bounds__(256)
void sgemm_nn(const float* __restrict__ A, const float* __restrict__ B,
              float* __restrict__ C,
              int M, int N, int K, int lda, int ldb, int ldc,
              long long aBS, long long bBS, long long cBS)
{
    __shared__ float As[16][64];
    __shared__ float Bs[16][64];

    const int tid = threadIdx.x;
    const int tx = tid & 15;
    const int ty = tid >> 4;
    const int m0 = blockIdx.y * 64;
    const int n0 = blockIdx.x * 64;

    const float* Ab = A + (long long)blockIdx.z * aBS;
    const float* Bb = B + (long long)blockIdx.z * bBS;
    float*       Cb = C + (long long)blockIdx.z * cBS;

    const int lr = tid >> 2;
    const int lk = (tid & 3) << 2;
    const int bkr = tid >> 4;
    const int bnc = (tid & 15) << 2;

    float acc[4][4];
    #pragma unroll
    for (int i = 0; i < 4; i++)
        #pragma unroll
        for (int j = 0; j < 4; j++) acc[i][j] = 0.f;

    for (int kt = 0; kt < K; kt += 16) {
        {
            int m = m0 + lr;
            float4 v = make_float4(0.f, 0.f, 0.f, 0.f);
            if (m < M) v = *(const float4*)(Ab + (size_t)m * lda + kt + lk);
            As[lk + 0][lr] = v.x; As[lk + 1][lr] = v.y;
            As[lk + 2][lr] = v.z; As[lk + 3][lr] = v.w;
        }
        {
            int n = n0 + bnc;
            float4 v = make_float4(0.f, 0.f, 0.f, 0.f);
            if (n < N) v = *(const float4*)(Bb + (size_t)(kt + bkr) * ldb + n);
            *(float4*)&Bs[bkr][bnc] = v;
        }
        __syncthreads();
        #pragma unroll
        for (int k = 0; k < 16; k++) {
            float a[4], b[4];
            *(float4*)a = *(const float4*)&As[k][ty << 2];
            *(float4*)b = *(const float4*)&Bs[k][tx << 2];
            #pragma unroll
            for (int i = 0; i < 4; i++)
                #pragma unroll
                for (int j = 0; j < 4; j++)
                    acc[i][j] += a[i] * b[j];
        }
        __syncthreads();
    }

    #pragma unroll
    for (int i = 0; i < 4; i++) {
        int m = m0 + (ty << 2) + i;
        if (m >= M) continue;
        #pragma unroll
        for (int j = 0; j < 4; j++) {
            int n = n0 + (tx << 2) + j;
            if (n < N) Cb[(size_t)m * ldc + n] = acc[i][j];
        }
    }
}

// ---------------- row softmax (in place) ----------------
__global__ __launch_bounds__(256)
void softmax_rows(float* __restrict__ data, int L)
{
    float* p = data + (size_t)blockIdx.x * L;
    __shared__ float red[256];
    const int tid = threadIdx.x;

    float m = -3.4e38f;
    for (int i = tid; i < L; i += 256) m = fmaxf(m, p[i]);
    red[tid] = m; __syncthreads();
    #pragma unroll
    for (int s = 128; s > 0; s >>= 1) {
        if (tid < s) red[tid] = fmaxf(red[tid], red[tid + s]);
        __syncthreads();
    }
    m = red[0]; __syncthreads();

    float sum = 0.f;
    for (int i = tid; i < L; i += 256) {
        float e = expf(p[i] - m);
        p[i] = e;
        sum += e;
    }
    red[tid] = sum; __syncthreads();
    #pragma unroll
    for (int s = 128; s > 0; s >>= 1) {
        if (tid < s) red[tid] += red[tid + s];
        __syncthreads();
    }
    const float inv = 1.f / red[0];
    for (int i = tid; i < L; i += 256) p[i] *= inv;
}

// ---------------- launch ----------------
extern "C" void kernel_launch(void* const* d_in, const int* in_sizes, int n_in,
                              void* d_out, int out_size)
{
    const float* inputs = (const float*)d_in[0];
    const float* h0     = (const float*)d_in[1];
    const float* c0     = (const float*)d_in[2];
    const float* Lst    = (const float*)d_in[3];
    const float* W_ih1  = (const float*)d_in[4];
    const float* W_hh1  = (const float*)d_in[5];
    const float* b_ih1  = (const float*)d_in[6];
    const float* b_hh1  = (const float*)d_in[7];
    const float* W_ih2  = (const float*)d_in[8];
    const float* W_hh2  = (const float*)d_in[9];
    const float* b_ih2  = (const float*)d_in[10];
    const float* b_hh2  = (const float*)d_in[11];
    const float* W_out  = (const float*)d_in[12];
    const float* b_out  = (const float*)d_in[13];
    float* out = (float*)d_out;

    void* p;
    cudaGetSymbolAddress(&p, g_X1);  float* X1  = (float*)p;
    cudaGetSymbolAddress(&p, g_H1);  float* H1  = (float*)p;
    cudaGetSymbolAddress(&p, g_S);   float* S   = (float*)p;
    cudaGetSymbolAddress(&p, g_CTX); float* CTX = (float*)p;
    cudaGetSymbolAddress(&p, g_X2);  float* X2  = (float*)p;
    cudaGetSymbolAddress(&p, g_HS);  float* HS  = (float*)p;

    // X1 = inputs @ W_ih1^T + b_ih1 + b_hh1
    {
        dim3 g(G4 / 64, (TT * BB) / 64, 1);
        sgemm_tn<<<g, 256>>>(inputs, W_ih1, X1, b_ih1, b_hh1,
                             TT * BB, G4, EE, EE, EE, G4, 0, 0, 0);
    }

    // layer-1 recurrence (persistent, flag-synced)
    flags_reset<<<1, 128>>>();
    lstm_seq<<<NBLK, 128>>>(X1, W_hh1, h0, c0, H1);

    // attention: S[t,b,u] = sum_h H1[t,b,h] * L[u,b,h]
    {
        dim3 g(UU / 64, TT / 64, BB);
        sgemm_tn<<<g, 256>>>(H1, Lst, S, nullptr, nullptr,
                             TT, UU, HH, BB * HH, BB * HH, BB * UU,
                             HH, HH, UU);
    }
    softmax_rows<<<TT * BB, 256>>>(S, UU);
    // CTX[t,b,h] = sum_u S[t,b,u] * L[u,b,h]
    {
        dim3 g(HH / 64, TT / 64, BB);
        sgemm_nn<<<g, 256>>>(S, Lst, CTX,
                             TT, HH, UU, BB * UU, BB * HH, BB * HH,
                             UU, HH, HH);
    }

    // X2 = CTX @ W_ih2^T + b_ih2 + b_hh2
    {
        dim3 g(G4 / 64, (TT * BB) / 64, 1);
        sgemm_tn<<<g, 256>>>(CTX, W_ih2, X2, b_ih2, b_hh2,
                             TT * BB, G4, HH, HH, HH, G4, 0, 0, 0);
    }

    // layer-2 recurrence (persistent, flag-synced)
    flags_reset<<<1, 128>>>();
    lstm_seq<<<NBLK, 128>>>(X2, W_hh2, h0 + BB * HH, c0 + BB * HH, HS);

    // logits = HS @ W_out^T + b_out -> softmax over V
    {
        dim3 g((VV + 63) / 64, (TT * BB) / 64, 1);
        sgemm_tn<<<g, 256>>>(HS, W_out, out, b_out, nullptr,
                             TT * BB, VV, HH, HH, HH, VV, 0, 0, 0);
    }
    softmax_rows<<<TT * BB, 256>>>(out, VV);
}